// round 10
// baseline (speedup 1.0000x reference)
#include <cuda_runtime.h>
#include <cuda_bf16.h>
#include <stdint.h>

// ---------------------------------------------------------------------------
// B=16, Lq=1024, Lkv=1424, DIM=384, HEADS=8, HEAD_DIM=48, TEM_LEN=400
// pre-split: fp32 -> bf16 hi/lo (A and W) once, elementwise
// projections: mma.sync bf16 hi/lo GEMM (3-product split)
// attention:   mma.sync flash, S 2-split (Qhi.Khi + Qlo.Khi), PV 3-split,
//              fixed-max softmax, V via ldmatrix.trans (row-major storage)
// ---------------------------------------------------------------------------

constexpr int B    = 16;
constexpr int H    = 8;
constexpr int DIM  = 384;
constexpr int HD   = 48;
constexpr int LQ   = 1024;
constexpr int LKV  = 1424;
constexpr int TEM  = 400;
constexpr float ATTN_SCALE = 0.14433756729740643f;  // 48^-0.5
constexpr float M_FIX = 12.0f;

using u32 = unsigned int;

// ---- scratch ---------------------------------------------------------------
__device__ __nv_bfloat16 g_ahi[B * LKV * DIM];      // pre-split A (q or kv)
__device__ __nv_bfloat16 g_alo[B * LKV * DIM];
__device__ __nv_bfloat16 g_whi[2 * DIM * DIM];      // pre-split W
__device__ __nv_bfloat16 g_wlo[2 * DIM * DIM];
__device__ __nv_bfloat16 g_qhi[B * H * LQ * HD];    // (b,h,q,d) pre-scaled
__device__ __nv_bfloat16 g_qlo[B * H * LQ * HD];
__device__ __nv_bfloat16 g_khi[B * H * LKV * HD];   // (b,h,s,d)
__device__ __nv_bfloat16 g_vhi[B * H * LKV * HD];   // (b,h,s,d) row-major
__device__ __nv_bfloat16 g_vlo[B * H * LKV * HD];
__device__ __nv_bfloat16 g_xhi[B * LQ * DIM];       // attention out hi/lo
__device__ __nv_bfloat16 g_xlo[B * LQ * DIM];

// ---- wrappers --------------------------------------------------------------
__device__ __forceinline__ u32 smu32(const void* p) {
    u32 a;
    asm("{ .reg .u64 t; cvta.to.shared.u64 t, %1; cvt.u32.u64 %0, t; }"
        : "=r"(a) : "l"(p));
    return a;
}
__device__ __forceinline__ void ldmx4(u32* r, u32 addr) {
    asm volatile("ldmatrix.sync.aligned.m8n8.x4.shared.b16 {%0,%1,%2,%3}, [%4];"
                 : "=r"(r[0]), "=r"(r[1]), "=r"(r[2]), "=r"(r[3]) : "r"(addr));
}
__device__ __forceinline__ void ldmx2(u32* r, u32 addr) {
    asm volatile("ldmatrix.sync.aligned.m8n8.x2.shared.b16 {%0,%1}, [%2];"
                 : "=r"(r[0]), "=r"(r[1]) : "r"(addr));
}
__device__ __forceinline__ void ldmx2t(u32* r, u32 addr) {
    asm volatile("ldmatrix.sync.aligned.m8n8.x2.trans.shared.b16 {%0,%1}, [%2];"
                 : "=r"(r[0]), "=r"(r[1]) : "r"(addr));
}
__device__ __forceinline__ void mma16816(float* d, const u32* a, const u32* b) {
    asm volatile(
        "mma.sync.aligned.m16n8k16.row.col.f32.bf16.bf16.f32 "
        "{%0,%1,%2,%3}, {%4,%5,%6,%7}, {%8,%9}, {%0,%1,%2,%3};"
        : "+f"(d[0]), "+f"(d[1]), "+f"(d[2]), "+f"(d[3])
        : "r"(a[0]), "r"(a[1]), "r"(a[2]), "r"(a[3]), "r"(b[0]), "r"(b[1]));
}
__device__ __forceinline__ u32 cvt2bf(float lo, float hi) {   // lo -> low 16
    u32 d; asm("cvt.rn.bf16x2.f32 %0, %1, %2;" : "=r"(d) : "f"(hi), "f"(lo));
    return d;
}
__device__ __forceinline__ u32 packbf(__nv_bfloat16 lo, __nv_bfloat16 hi) {
    return ((u32)__bfloat16_as_ushort(hi) << 16) | (u32)__bfloat16_as_ushort(lo);
}

// ---------------------------------------------------------------------------
// pre-split: fp32 -> bf16 hi + bf16 lo residual
// ---------------------------------------------------------------------------
__global__ void ps_split(const float4* __restrict__ src,
                         uint2* __restrict__ hi, uint2* __restrict__ lo, int n4)
{
    int i = blockIdx.x * blockDim.x + threadIdx.x;
    if (i >= n4) return;
    float4 v = src[i];
    __nv_bfloat16 h0 = __float2bfloat16(v.x), h1 = __float2bfloat16(v.y);
    __nv_bfloat16 h2 = __float2bfloat16(v.z), h3 = __float2bfloat16(v.w);
    hi[i] = make_uint2(packbf(h0, h1), packbf(h2, h3));
    lo[i] = make_uint2(
        cvt2bf(v.x - __bfloat162float(h0), v.y - __bfloat162float(h1)),
        cvt2bf(v.z - __bfloat162float(h2), v.w - __bfloat162float(h3)));
}

// ---------------------------------------------------------------------------
// Tensor-core GEMM on pre-split operands.  out[m][n] = sum A[m][k] W[n][k] + b
// Block 128x128, 256 threads (8 warps: 4m x 2n), K=384 in chunks of 32.
// MODE 0: q-proj -> g_qhi/lo (pre-scaled)
// MODE 1: kv-proj -> g_khi (hi only) + g_vhi/lo row-major (+masks)
// MODE 2: out-proj -> fp32 d_out
// ---------------------------------------------------------------------------
constexpr int GST = 40;   // bf16 row stride (80B) -> conflict-free ldmatrix

template <int MODE>
__device__ __forceinline__ void scatter_elem(
    int m, int n, float v,
    const float* __restrict__ bias,
    const float* __restrict__ tmask, const float* __restrict__ smask,
    float* __restrict__ out)
{
    v += bias[n];
    if (MODE == 0) {
        int b  = m >> 10;
        int qi = m & 1023;
        int h  = n / HD;
        int d  = n - h * HD;
        float vs = v * ATTN_SCALE;
        __nv_bfloat16 hb = __float2bfloat16(vs);
        float lo = vs - __bfloat162float(hb);
        size_t o = ((size_t)(b * H + h) * LQ + qi) * HD + d;
        g_qhi[o] = hb;
        g_qlo[o] = __float2bfloat16(lo);
    } else if (MODE == 1) {
        int b = m / LKV;
        int s = m - b * LKV;
        if (n < DIM) {
            int h = n / HD, d = n - h * HD;
            g_khi[((size_t)(b * H + h) * LKV + s) * HD + d] = __float2bfloat16(v);
        } else {
            int nv = n - DIM;
            float mv = (s < TEM)
                ? tmask[((size_t)(b * TEM + s)) * DIM + nv]
                : smask[((size_t)(b * (LKV - TEM) + (s - TEM))) * DIM + nv];
            v += mv;
            int h = nv / HD, d = nv - h * HD;
            __nv_bfloat16 hb = __float2bfloat16(v);
            float lo = v - __bfloat162float(hb);
            size_t o = ((size_t)(b * H + h) * LKV + s) * HD + d;
            g_vhi[o] = hb;
            g_vlo[o] = __float2bfloat16(lo);
        }
    } else {
        out[(size_t)m * DIM + n] = v;
    }
}

template <int MODE>
__global__ __launch_bounds__(256) void mgemm_kernel(
    const __nv_bfloat16* __restrict__ Ahi, const __nv_bfloat16* __restrict__ Alo,
    const __nv_bfloat16* __restrict__ Whi, const __nv_bfloat16* __restrict__ Wlo,
    const float* __restrict__ bias,
    const float* __restrict__ tmask, const float* __restrict__ smask,
    float* __restrict__ out)
{
    __shared__ __align__(16) __nv_bfloat16 Ah[128][GST];
    __shared__ __align__(16) __nv_bfloat16 Al[128][GST];
    __shared__ __align__(16) __nv_bfloat16 Bh[128][GST];
    __shared__ __align__(16) __nv_bfloat16 Bl[128][GST];

    const int m0   = blockIdx.y * 128;
    const int n0   = blockIdx.x * 128;
    const int tid  = threadIdx.x;
    const int warp = tid >> 5;
    const int lane = tid & 31;
    const int l16  = lane & 15;
    const int wm   = warp & 3;
    const int wn   = warp >> 2;

    const u32 sAh = smu32(&Ah[0][0]), sAl = smu32(&Al[0][0]);
    const u32 sBh = smu32(&Bh[0][0]), sBl = smu32(&Bl[0][0]);

    float acc[2][8][4];
#pragma unroll
    for (int mi = 0; mi < 2; mi++)
#pragma unroll
        for (int nj = 0; nj < 8; nj++)
#pragma unroll
            for (int j = 0; j < 4; j++) acc[mi][nj][j] = 0.0f;

    const int lrow = tid >> 1;            // 0..127
    const int lkc  = (tid & 1) * 16;      // 0 or 16
    const __nv_bfloat16* pAh = Ahi + (size_t)(m0 + lrow) * DIM + lkc;
    const __nv_bfloat16* pAl = Alo + (size_t)(m0 + lrow) * DIM + lkc;
    const __nv_bfloat16* pWh = Whi + (size_t)(n0 + lrow) * DIM + lkc;
    const __nv_bfloat16* pWl = Wlo + (size_t)(n0 + lrow) * DIM + lkc;

    for (int k0 = 0; k0 < DIM; k0 += 32) {
        __syncthreads();
#pragma unroll
        for (int j = 0; j < 2; j++) {
            *(uint4*)&Ah[lrow][lkc + j * 8] = *(const uint4*)(pAh + k0 + j * 8);
            *(uint4*)&Al[lrow][lkc + j * 8] = *(const uint4*)(pAl + k0 + j * 8);
            *(uint4*)&Bh[lrow][lkc + j * 8] = *(const uint4*)(pWh + k0 + j * 8);
            *(uint4*)&Bl[lrow][lkc + j * 8] = *(const uint4*)(pWl + k0 + j * 8);
        }
        __syncthreads();

#pragma unroll
        for (int ks = 0; ks < 2; ks++) {
            u32 ahf[2][4], alf[2][4];
#pragma unroll
            for (int mi = 0; mi < 2; mi++) {
                u32 aoff = (u32)((wm * 32 + mi * 16 + l16) * (GST * 2)
                                 + (lane >> 4) * 16 + ks * 32);
                ldmx4(ahf[mi], sAh + aoff);
                ldmx4(alf[mi], sAl + aoff);
            }
#pragma unroll
            for (int nj = 0; nj < 8; nj++) {
                u32 boff = (u32)((wn * 64 + nj * 8 + (l16 & 7)) * (GST * 2)
                                 + (l16 >> 3) * 16 + ks * 32);
                u32 bhf[2], blf[2];
                ldmx2(bhf, sBh + boff);
                ldmx2(blf, sBl + boff);
#pragma unroll
                for (int mi = 0; mi < 2; mi++) {
                    mma16816(acc[mi][nj], ahf[mi], bhf);
                    mma16816(acc[mi][nj], alf[mi], bhf);
                    mma16816(acc[mi][nj], ahf[mi], blf);
                }
            }
        }
    }

#pragma unroll
    for (int mi = 0; mi < 2; mi++) {
#pragma unroll
        for (int rh = 0; rh < 2; rh++) {
            int m = m0 + wm * 32 + mi * 16 + rh * 8 + (lane >> 2);
#pragma unroll
            for (int nj = 0; nj < 8; nj++) {
                int n = n0 + wn * 64 + nj * 8 + (lane & 3) * 2;
                scatter_elem<MODE>(m, n,     acc[mi][nj][rh * 2 + 0], bias, tmask, smask, out);
                scatter_elem<MODE>(m, n + 1, acc[mi][nj][rh * 2 + 1], bias, tmask, smask, out);
            }
        }
    }
}

// ---------------------------------------------------------------------------
// mma.sync flash attention.  Block = (b, h, 64-q tile), 128 threads (4 warps).
// S = Qhi.Khi + Qlo.Khi (2-split); PV = Phi.Vhi + Plo.Vhi + Phi.Vlo.
// V stored row-major [s][d]; B fragments via ldmatrix.trans.
// ---------------------------------------------------------------------------
constexpr int QK_STRIDE = 56;   // 112B rows -> conflict-free ldmatrix

__global__ __launch_bounds__(128) void attn_kernel(const float* __restrict__ pos)
{
    __shared__ __align__(16) __nv_bfloat16 Qh[64][QK_STRIDE];
    __shared__ __align__(16) __nv_bfloat16 Ql[64][QK_STRIDE];
    __shared__ __align__(16) __nv_bfloat16 Kh[64][QK_STRIDE];
    __shared__ __align__(16) __nv_bfloat16 Vh[64][QK_STRIDE];
    __shared__ __align__(16) __nv_bfloat16 Vl[64][QK_STRIDE];

    const int tid   = threadIdx.x;
    const int warp  = tid >> 5;
    const int lane  = tid & 31;
    const int l16   = lane & 15;
    const int bid   = blockIdx.x;
    const int b     = bid & 15;            // batch fastest: pos L2 reuse x16
    const int qt    = (bid >> 4) & 15;
    const int h     = bid >> 8;
    const int q0    = qt * 64;
    const int bh    = b * H + h;
    const int qrow0 = warp * 16;

    const u32 sQh = smu32(&Qh[0][0]), sQl = smu32(&Ql[0][0]);
    const u32 sKh = smu32(&Kh[0][0]);
    const u32 sVh = smu32(&Vh[0][0]), sVl = smu32(&Vl[0][0]);

    {
        const __nv_bfloat16* qh = g_qhi + ((size_t)bh * LQ + q0) * HD;
        const __nv_bfloat16* ql = g_qlo + ((size_t)bh * LQ + q0) * HD;
#pragma unroll
        for (int l = 0; l < 3; l++) {
            int idx = tid + 128 * l;
            int row = idx / 6, c = idx % 6;
            *(uint4*)&Qh[row][c * 8] = *(const uint4*)(qh + row * HD + c * 8);
            *(uint4*)&Ql[row][c * 8] = *(const uint4*)(ql + row * HD + c * 8);
        }
    }
    __syncthreads();

    u32 qfh[3][4], qfl[3][4];
    {
        u32 qoff = (u32)((qrow0 + l16) * (QK_STRIDE * 2) + (lane >> 4) * 16);
#pragma unroll
        for (int ks = 0; ks < 3; ks++) {
            ldmx4(qfh[ks], sQh + qoff + ks * 32);
            ldmx4(qfl[ks], sQl + qoff + ks * 32);
        }
    }

    const __nv_bfloat16* kh = g_khi + (size_t)bh * LKV * HD;
    const __nv_bfloat16* vh = g_vhi + (size_t)bh * LKV * HD;
    const __nv_bfloat16* vl = g_vlo + (size_t)bh * LKV * HD;

    const int rowA = q0 + qrow0 + (lane >> 2);
    const float* posA = pos + ((size_t)h * LQ + rowA) * LKV;
    const float* posB = posA + (size_t)8 * LKV;

    float oacc[6][4];
#pragma unroll
    for (int n = 0; n < 6; n++)
#pragma unroll
        for (int j = 0; j < 4; j++) oacc[n][j] = 0.0f;
    float lsum0 = 0.0f, lsum1 = 0.0f;

    constexpr int NT = (LKV + 63) / 64;  // 23

    for (int t = 0; t < NT; t++) {
        const int kv0 = t * 64;

        __syncthreads();

#pragma unroll
        for (int l = 0; l < 3; l++) {
            int idx = tid + 128 * l;
            int row = idx / 6, c = idx % 6;
            int srow = kv0 + row; if (srow >= LKV) srow = LKV - 1;
            *(uint4*)&Kh[row][c * 8] = *(const uint4*)(kh + (size_t)srow * HD + c * 8);
            *(uint4*)&Vh[row][c * 8] = *(const uint4*)(vh + (size_t)srow * HD + c * 8);
            *(uint4*)&Vl[row][c * 8] = *(const uint4*)(vl + (size_t)srow * HD + c * 8);
        }
        __syncthreads();

        // ---- S = Qhi.Khi + Qlo.Khi ----
        float sacc[8][4];
#pragma unroll
        for (int n = 0; n < 8; n++)
#pragma unroll
            for (int j = 0; j < 4; j++) sacc[n][j] = 0.0f;

#pragma unroll
        for (int nn = 0; nn < 8; nn++) {
            u32 koff = (u32)((nn * 8 + (l16 & 7)) * (QK_STRIDE * 2) + (l16 >> 3) * 16);
#pragma unroll
            for (int ks = 0; ks < 3; ks++) {
                u32 bh2[2];
                ldmx2(bh2, sKh + koff + ks * 32);
                mma16816(sacc[nn], qfh[ks], bh2);
                mma16816(sacc[nn], qfl[ks], bh2);
            }
        }

        // ---- softmax: p = exp(s + pos - M_FIX) ----
#pragma unroll
        for (int nn = 0; nn < 8; nn++) {
            int col = kv0 + nn * 8 + (lane & 3) * 2;
            if (col < LKV) {
                float2 pA = *(const float2*)(posA + col);
                float2 pB = *(const float2*)(posB + col);
                float p0 = __expf(sacc[nn][0] + pA.x - M_FIX);
                float p1 = __expf(sacc[nn][1] + pA.y - M_FIX);
                float p2 = __expf(sacc[nn][2] + pB.x - M_FIX);
                float p3 = __expf(sacc[nn][3] + pB.y - M_FIX);
                sacc[nn][0] = p0; sacc[nn][1] = p1;
                sacc[nn][2] = p2; sacc[nn][3] = p3;
                lsum0 += p0 + p1;
                lsum1 += p2 + p3;
            } else {
                sacc[nn][0] = 0.f; sacc[nn][1] = 0.f;
                sacc[nn][2] = 0.f; sacc[nn][3] = 0.f;
            }
        }

        // ---- O += Phi.Vhi + Plo.Vhi + Phi.Vlo ----
#pragma unroll
        for (int kk = 0; kk < 4; kk++) {
            u32 pah[4], pal[4];
#pragma unroll
            for (int half = 0; half < 2; half++) {
                int cn = 2 * kk + half;
                float p0 = sacc[cn][0], p1 = sacc[cn][1];
                float p2 = sacc[cn][2], p3 = sacc[cn][3];
                float h0 = __bfloat162float(__float2bfloat16(p0));
                float h1 = __bfloat162float(__float2bfloat16(p1));
                float h2 = __bfloat162float(__float2bfloat16(p2));
                float h3 = __bfloat162float(__float2bfloat16(p3));
                if (half == 0) {
                    pah[0] = cvt2bf(p0, p1);
                    pah[1] = cvt2bf(p2, p3);
                    pal[0] = cvt2bf(p0 - h0, p1 - h1);
                    pal[1] = cvt2bf(p2 - h2, p3 - h3);
                } else {
                    pah[2] = cvt2bf(p0, p1);
                    pah[3] = cvt2bf(p2, p3);
                    pal[2] = cvt2bf(p0 - h0, p1 - h1);
                    pal[3] = cvt2bf(p2 - h2, p3 - h3);
                }
            }
#pragma unroll
            for (int nd = 0; nd < 6; nd++) {
                u32 voff = (u32)((kk * 16 + l16) * (QK_STRIDE * 2) + nd * 16);
                u32 vfh[2], vfl[2];
                ldmx2t(vfh, sVh + voff);
                ldmx2t(vfl, sVl + voff);
                mma16816(oacc[nd], pah, vfh);
                mma16816(oacc[nd], pal, vfh);
                mma16816(oacc[nd], pah, vfl);
            }
        }
    }

    lsum0 += __shfl_xor_sync(0xffffffffu, lsum0, 1);
    lsum0 += __shfl_xor_sync(0xffffffffu, lsum0, 2);
    lsum1 += __shfl_xor_sync(0xffffffffu, lsum1, 1);
    lsum1 += __shfl_xor_sync(0xffffffffu, lsum1, 2);
    float inv0 = 1.0f / lsum0;
    float inv1 = 1.0f / lsum1;

    // ---- write hi/lo split of O (feeds pre-split out-proj) ----
    size_t baseA = ((size_t)(b * LQ + rowA)) * DIM + h * HD;
    size_t baseB = baseA + (size_t)8 * DIM;
#pragma unroll
    for (int nd = 0; nd < 6; nd++) {
        int c = nd * 8 + (lane & 3) * 2;
        float a0 = oacc[nd][0] * inv0, a1 = oacc[nd][1] * inv0;
        float b0 = oacc[nd][2] * inv1, b1 = oacc[nd][3] * inv1;
        __nv_bfloat16 ha0 = __float2bfloat16(a0), ha1 = __float2bfloat16(a1);
        __nv_bfloat16 hb0 = __float2bfloat16(b0), hb1 = __float2bfloat16(b1);
        *(u32*)(g_xhi + baseA + c) = packbf(ha0, ha1);
        *(u32*)(g_xlo + baseA + c) = cvt2bf(a0 - __bfloat162float(ha0),
                                            a1 - __bfloat162float(ha1));
        *(u32*)(g_xhi + baseB + c) = packbf(hb0, hb1);
        *(u32*)(g_xlo + baseB + c) = cvt2bf(b0 - __bfloat162float(hb0),
                                            b1 - __bfloat162float(hb1));
    }
}

// ---------------------------------------------------------------------------
extern "C" void kernel_launch(void* const* d_in, const int* in_sizes, int n_in,
                              void* d_out, int out_size)
{
    const float* tem_mask    = (const float*)d_in[0];
    const float* search_mask = (const float*)d_in[1];
    const float* q           = (const float*)d_in[2];
    const float* kv          = (const float*)d_in[3];
    const float* attn_pos    = (const float*)d_in[4];
    const float* q_w         = (const float*)d_in[5];
    const float* q_b         = (const float*)d_in[6];
    const float* kv_w        = (const float*)d_in[7];
    const float* kv_b        = (const float*)d_in[8];
    const float* proj_w      = (const float*)d_in[9];
    const float* proj_b      = (const float*)d_in[10];
    float* out = (float*)d_out;

    __nv_bfloat16 *ahi = nullptr, *alo = nullptr, *whi = nullptr, *wlo = nullptr;
    cudaGetSymbolAddress((void**)&ahi, g_ahi);
    cudaGetSymbolAddress((void**)&alo, g_alo);
    cudaGetSymbolAddress((void**)&whi, g_whi);
    cudaGetSymbolAddress((void**)&wlo, g_wlo);
    __nv_bfloat16 *xhi = nullptr, *xlo = nullptr;
    cudaGetSymbolAddress((void**)&xhi, g_xhi);
    cudaGetSymbolAddress((void**)&xlo, g_xlo);

    const int n4_q  = B * LQ * DIM / 4;     // 1572864
    const int n4_kv = B * LKV * DIM / 4;    // 2187264
    const int n4_qw = DIM * DIM / 4;        // 36864
    const int n4_kw = 2 * DIM * DIM / 4;    // 73728

    // q projection
    ps_split<<<(n4_q + 255) / 256, 256>>>((const float4*)q, (uint2*)ahi, (uint2*)alo, n4_q);
    ps_split<<<(n4_qw + 255) / 256, 256>>>((const float4*)q_w, (uint2*)whi, (uint2*)wlo, n4_qw);
    mgemm_kernel<0><<<dim3(3, 128), 256>>>(ahi, alo, whi, wlo, q_b, nullptr, nullptr, nullptr);

    // kv projection
    ps_split<<<(n4_kv + 255) / 256, 256>>>((const float4*)kv, (uint2*)ahi, (uint2*)alo, n4_kv);
    ps_split<<<(n4_kw + 255) / 256, 256>>>((const float4*)kv_w, (uint2*)whi, (uint2*)wlo, n4_kw);
    mgemm_kernel<1><<<dim3(6, 178), 256>>>(ahi, alo, whi, wlo, kv_b, tem_mask, search_mask, nullptr);

    // attention
    attn_kernel<<<B * H * (LQ / 64), 128>>>(attn_pos);

    // output projection
    ps_split<<<(n4_qw + 255) / 256, 256>>>((const float4*)proj_w, (uint2*)whi, (uint2*)wlo, n4_qw);
    mgemm_kernel<2><<<dim3(3, 128), 256>>>(xhi, xlo, whi, wlo, proj_b, nullptr, nullptr, out);
}

// round 11
// speedup vs baseline: 1.1392x; 1.1392x over previous
#include <cuda_runtime.h>
#include <cuda_bf16.h>
#include <stdint.h>

// ---------------------------------------------------------------------------
// B=16, Lq=1024, Lkv=1424, DIM=384, HEADS=8, HEAD_DIM=48, TEM_LEN=400
// pre-split: fp32 -> bf16 hi/lo once, elementwise
// projections: mma.sync bf16 hi/lo GEMM (3-product split)
// attention:   mma.sync flash, cp.async double-buffered K/V pipeline,
//              S 2-split, PV 3-split, fixed-max softmax, pos prefetch
// ---------------------------------------------------------------------------

constexpr int B    = 16;
constexpr int H    = 8;
constexpr int DIM  = 384;
constexpr int HD   = 48;
constexpr int LQ   = 1024;
constexpr int LKV  = 1424;
constexpr int TEM  = 400;
constexpr float ATTN_SCALE = 0.14433756729740643f;  // 48^-0.5
constexpr float M_FIX = 12.0f;

using u32 = unsigned int;

// ---- scratch ---------------------------------------------------------------
__device__ __nv_bfloat16 g_ahi[B * LKV * DIM];
__device__ __nv_bfloat16 g_alo[B * LKV * DIM];
__device__ __nv_bfloat16 g_whi[2 * DIM * DIM];
__device__ __nv_bfloat16 g_wlo[2 * DIM * DIM];
__device__ __nv_bfloat16 g_qhi[B * H * LQ * HD];    // (b,h,q,d) pre-scaled
__device__ __nv_bfloat16 g_qlo[B * H * LQ * HD];
__device__ __nv_bfloat16 g_khi[B * H * LKV * HD];   // (b,h,s,d)
__device__ __nv_bfloat16 g_vhi[B * H * LKV * HD];   // (b,h,s,d) row-major
__device__ __nv_bfloat16 g_vlo[B * H * LKV * HD];
__device__ __nv_bfloat16 g_xhi[B * LQ * DIM];
__device__ __nv_bfloat16 g_xlo[B * LQ * DIM];

// ---- wrappers --------------------------------------------------------------
__device__ __forceinline__ u32 smu32(const void* p) {
    u32 a;
    asm("{ .reg .u64 t; cvta.to.shared.u64 t, %1; cvt.u32.u64 %0, t; }"
        : "=r"(a) : "l"(p));
    return a;
}
__device__ __forceinline__ void ldmx4(u32* r, u32 addr) {
    asm volatile("ldmatrix.sync.aligned.m8n8.x4.shared.b16 {%0,%1,%2,%3}, [%4];"
                 : "=r"(r[0]), "=r"(r[1]), "=r"(r[2]), "=r"(r[3]) : "r"(addr));
}
__device__ __forceinline__ void ldmx2(u32* r, u32 addr) {
    asm volatile("ldmatrix.sync.aligned.m8n8.x2.shared.b16 {%0,%1}, [%2];"
                 : "=r"(r[0]), "=r"(r[1]) : "r"(addr));
}
__device__ __forceinline__ void ldmx2t(u32* r, u32 addr) {
    asm volatile("ldmatrix.sync.aligned.m8n8.x2.trans.shared.b16 {%0,%1}, [%2];"
                 : "=r"(r[0]), "=r"(r[1]) : "r"(addr));
}
__device__ __forceinline__ void mma16816(float* d, const u32* a, const u32* b) {
    asm volatile(
        "mma.sync.aligned.m16n8k16.row.col.f32.bf16.bf16.f32 "
        "{%0,%1,%2,%3}, {%4,%5,%6,%7}, {%8,%9}, {%0,%1,%2,%3};"
        : "+f"(d[0]), "+f"(d[1]), "+f"(d[2]), "+f"(d[3])
        : "r"(a[0]), "r"(a[1]), "r"(a[2]), "r"(a[3]), "r"(b[0]), "r"(b[1]));
}
__device__ __forceinline__ u32 cvt2bf(float lo, float hi) {   // lo -> low 16
    u32 d; asm("cvt.rn.bf16x2.f32 %0, %1, %2;" : "=r"(d) : "f"(hi), "f"(lo));
    return d;
}
__device__ __forceinline__ u32 packbf(__nv_bfloat16 lo, __nv_bfloat16 hi) {
    return ((u32)__bfloat16_as_ushort(hi) << 16) | (u32)__bfloat16_as_ushort(lo);
}
__device__ __forceinline__ void cpa16(u32 dst, const void* src) {
    asm volatile("cp.async.cg.shared.global [%0], [%1], 16;"
                 :: "r"(dst), "l"(src));
}
__device__ __forceinline__ void cpa_commit() {
    asm volatile("cp.async.commit_group;");
}
__device__ __forceinline__ void cpa_wait1() {
    asm volatile("cp.async.wait_group 1;");
}

// ---------------------------------------------------------------------------
// pre-split: fp32 -> bf16 hi + bf16 lo residual
// ---------------------------------------------------------------------------
__global__ void ps_split(const float4* __restrict__ src,
                         uint2* __restrict__ hi, uint2* __restrict__ lo, int n4)
{
    int i = blockIdx.x * blockDim.x + threadIdx.x;
    if (i >= n4) return;
    float4 v = src[i];
    __nv_bfloat16 h0 = __float2bfloat16(v.x), h1 = __float2bfloat16(v.y);
    __nv_bfloat16 h2 = __float2bfloat16(v.z), h3 = __float2bfloat16(v.w);
    hi[i] = make_uint2(packbf(h0, h1), packbf(h2, h3));
    lo[i] = make_uint2(
        cvt2bf(v.x - __bfloat162float(h0), v.y - __bfloat162float(h1)),
        cvt2bf(v.z - __bfloat162float(h2), v.w - __bfloat162float(h3)));
}

// ---------------------------------------------------------------------------
// Tensor-core GEMM on pre-split operands (unchanged from R9)
// ---------------------------------------------------------------------------
constexpr int GST = 40;

template <int MODE>
__device__ __forceinline__ void scatter_elem(
    int m, int n, float v,
    const float* __restrict__ bias,
    const float* __restrict__ tmask, const float* __restrict__ smask,
    float* __restrict__ out)
{
    v += bias[n];
    if (MODE == 0) {
        int b  = m >> 10;
        int qi = m & 1023;
        int h  = n / HD;
        int d  = n - h * HD;
        float vs = v * ATTN_SCALE;
        __nv_bfloat16 hb = __float2bfloat16(vs);
        float lo = vs - __bfloat162float(hb);
        size_t o = ((size_t)(b * H + h) * LQ + qi) * HD + d;
        g_qhi[o] = hb;
        g_qlo[o] = __float2bfloat16(lo);
    } else if (MODE == 1) {
        int b = m / LKV;
        int s = m - b * LKV;
        if (n < DIM) {
            int h = n / HD, d = n - h * HD;
            g_khi[((size_t)(b * H + h) * LKV + s) * HD + d] = __float2bfloat16(v);
        } else {
            int nv = n - DIM;
            float mv = (s < TEM)
                ? tmask[((size_t)(b * TEM + s)) * DIM + nv]
                : smask[((size_t)(b * (LKV - TEM) + (s - TEM))) * DIM + nv];
            v += mv;
            int h = nv / HD, d = nv - h * HD;
            __nv_bfloat16 hb = __float2bfloat16(v);
            float lo = v - __bfloat162float(hb);
            size_t o = ((size_t)(b * H + h) * LKV + s) * HD + d;
            g_vhi[o] = hb;
            g_vlo[o] = __float2bfloat16(lo);
        }
    } else {
        out[(size_t)m * DIM + n] = v;
    }
}

template <int MODE>
__global__ __launch_bounds__(256) void mgemm_kernel(
    const __nv_bfloat16* __restrict__ Ahi, const __nv_bfloat16* __restrict__ Alo,
    const __nv_bfloat16* __restrict__ Whi, const __nv_bfloat16* __restrict__ Wlo,
    const float* __restrict__ bias,
    const float* __restrict__ tmask, const float* __restrict__ smask,
    float* __restrict__ out)
{
    __shared__ __align__(16) __nv_bfloat16 Ah[128][GST];
    __shared__ __align__(16) __nv_bfloat16 Al[128][GST];
    __shared__ __align__(16) __nv_bfloat16 Bh[128][GST];
    __shared__ __align__(16) __nv_bfloat16 Bl[128][GST];

    const int m0   = blockIdx.y * 128;
    const int n0   = blockIdx.x * 128;
    const int tid  = threadIdx.x;
    const int warp = tid >> 5;
    const int lane = tid & 31;
    const int l16  = lane & 15;
    const int wm   = warp & 3;
    const int wn   = warp >> 2;

    const u32 sAh = smu32(&Ah[0][0]), sAl = smu32(&Al[0][0]);
    const u32 sBh = smu32(&Bh[0][0]), sBl = smu32(&Bl[0][0]);

    float acc[2][8][4];
#pragma unroll
    for (int mi = 0; mi < 2; mi++)
#pragma unroll
        for (int nj = 0; nj < 8; nj++)
#pragma unroll
            for (int j = 0; j < 4; j++) acc[mi][nj][j] = 0.0f;

    const int lrow = tid >> 1;
    const int lkc  = (tid & 1) * 16;
    const __nv_bfloat16* pAh = Ahi + (size_t)(m0 + lrow) * DIM + lkc;
    const __nv_bfloat16* pAl = Alo + (size_t)(m0 + lrow) * DIM + lkc;
    const __nv_bfloat16* pWh = Whi + (size_t)(n0 + lrow) * DIM + lkc;
    const __nv_bfloat16* pWl = Wlo + (size_t)(n0 + lrow) * DIM + lkc;

    for (int k0 = 0; k0 < DIM; k0 += 32) {
        __syncthreads();
#pragma unroll
        for (int j = 0; j < 2; j++) {
            *(uint4*)&Ah[lrow][lkc + j * 8] = *(const uint4*)(pAh + k0 + j * 8);
            *(uint4*)&Al[lrow][lkc + j * 8] = *(const uint4*)(pAl + k0 + j * 8);
            *(uint4*)&Bh[lrow][lkc + j * 8] = *(const uint4*)(pWh + k0 + j * 8);
            *(uint4*)&Bl[lrow][lkc + j * 8] = *(const uint4*)(pWl + k0 + j * 8);
        }
        __syncthreads();

#pragma unroll
        for (int ks = 0; ks < 2; ks++) {
            u32 ahf[2][4], alf[2][4];
#pragma unroll
            for (int mi = 0; mi < 2; mi++) {
                u32 aoff = (u32)((wm * 32 + mi * 16 + l16) * (GST * 2)
                                 + (lane >> 4) * 16 + ks * 32);
                ldmx4(ahf[mi], sAh + aoff);
                ldmx4(alf[mi], sAl + aoff);
            }
#pragma unroll
            for (int nj = 0; nj < 8; nj++) {
                u32 boff = (u32)((wn * 64 + nj * 8 + (l16 & 7)) * (GST * 2)
                                 + (l16 >> 3) * 16 + ks * 32);
                u32 bhf[2], blf[2];
                ldmx2(bhf, sBh + boff);
                ldmx2(blf, sBl + boff);
#pragma unroll
                for (int mi = 0; mi < 2; mi++) {
                    mma16816(acc[mi][nj], ahf[mi], bhf);
                    mma16816(acc[mi][nj], alf[mi], bhf);
                    mma16816(acc[mi][nj], ahf[mi], blf);
                }
            }
        }
    }

#pragma unroll
    for (int mi = 0; mi < 2; mi++) {
#pragma unroll
        for (int rh = 0; rh < 2; rh++) {
            int m = m0 + wm * 32 + mi * 16 + rh * 8 + (lane >> 2);
#pragma unroll
            for (int nj = 0; nj < 8; nj++) {
                int n = n0 + wn * 64 + nj * 8 + (lane & 3) * 2;
                scatter_elem<MODE>(m, n,     acc[mi][nj][rh * 2 + 0], bias, tmask, smask, out);
                scatter_elem<MODE>(m, n + 1, acc[mi][nj][rh * 2 + 1], bias, tmask, smask, out);
            }
        }
    }
}

// ---------------------------------------------------------------------------
// Flash attention, cp.async double-buffered.
// Block = (b, h, 64-q tile), 128 threads (4 warps).
// smem layout (bytes), row stride 112:
//   buf0: Kh 0..7168, Vh 7168.., Vl 14336..       (21504)
//   buf1: 21504.. (overlays Q staging: Qh@21504, Ql@28672 — dead after frags)
// ---------------------------------------------------------------------------
constexpr int KSTB  = 112;     // bytes per smem row (56 bf16)
constexpr int R_VH  = 7168;
constexpr int R_VL  = 14336;
constexpr int BUFSZ = 21504;
constexpr int SMQH  = 21504;
constexpr int SMQL  = 28672;

__global__ __launch_bounds__(128) void attn_kernel(const float* __restrict__ pos)
{
    __shared__ __align__(16) char sm[43008];
    const u32 sb = smu32(sm);

    const int tid   = threadIdx.x;
    const int warp  = tid >> 5;
    const int lane  = tid & 31;
    const int l16   = lane & 15;
    const int bid   = blockIdx.x;
    const int b     = bid & 15;            // batch fastest: pos L2 reuse x16
    const int qt    = (bid >> 4) & 15;
    const int h     = bid >> 8;
    const int q0    = qt * 64;
    const int bh    = b * H + h;
    const int qrow0 = warp * 16;

    const __nv_bfloat16* kh = g_khi + (size_t)bh * LKV * HD;
    const __nv_bfloat16* vh = g_vhi + (size_t)bh * LKV * HD;
    const __nv_bfloat16* vl = g_vlo + (size_t)bh * LKV * HD;

    // async fill of one kv tile (Kh/Vh/Vl, 64 rows x 96B) into buffer
    auto cp_fill = [&](u32 bufbase, int tile) {
        const int kv0 = tile * 64;
#pragma unroll
        for (int l = 0; l < 9; l++) {
            int i   = tid + 128 * l;          // 0..1151
            int arr = i / 384;
            int rem = i - arr * 384;
            int row = rem / 6;
            int ch  = rem - row * 6;
            int srow = kv0 + row; if (srow >= LKV) srow = LKV - 1;
            const __nv_bfloat16* src =
                (arr == 0 ? kh : (arr == 1 ? vh : vl)) + (size_t)srow * HD + ch * 8;
            cpa16(bufbase + arr * 7168 + row * KSTB + ch * 16, src);
        }
    };

    // ---- Q staging (region of buf1) + start tile0 fill ----
    {
        const __nv_bfloat16* qh = g_qhi + ((size_t)bh * LQ + q0) * HD;
        const __nv_bfloat16* ql = g_qlo + ((size_t)bh * LQ + q0) * HD;
#pragma unroll
        for (int l = 0; l < 3; l++) {
            int idx = tid + 128 * l;
            int row = idx / 6, c = idx % 6;
            *(uint4*)(sm + SMQH + row * KSTB + c * 16) = *(const uint4*)(qh + row * HD + c * 8);
            *(uint4*)(sm + SMQL + row * KSTB + c * 16) = *(const uint4*)(ql + row * HD + c * 8);
        }
    }
    cp_fill(sb, 0);            // buf0 <- tile 0 (disjoint from Q staging)
    cpa_commit();
    __syncthreads();

    // ---- Q fragments ----
    u32 qfh[3][4], qfl[3][4];
    {
        u32 qo = (u32)((qrow0 + l16) * KSTB + (lane >> 4) * 16);
#pragma unroll
        for (int ks = 0; ks < 3; ks++) {
            ldmx4(qfh[ks], sb + SMQH + qo + ks * 32);
            ldmx4(qfl[ks], sb + SMQL + qo + ks * 32);
        }
    }
    __syncthreads();           // Q staging dead -> buf1 may be filled
    cp_fill(sb + BUFSZ, 1);    // buf1 <- tile 1
    cpa_commit();

    const int rowA = q0 + qrow0 + (lane >> 2);
    const float* posA = pos + ((size_t)h * LQ + rowA) * LKV;
    const float* posB = posA + (size_t)8 * LKV;

    float oacc[6][4];
#pragma unroll
    for (int n = 0; n < 6; n++)
#pragma unroll
        for (int j = 0; j < 4; j++) oacc[n][j] = 0.0f;
    float lsum0 = 0.0f, lsum1 = 0.0f;

    constexpr int NT = (LKV + 63) / 64;  // 23

    for (int t = 0; t < NT; t++) {
        const int kv0 = t * 64;
        cpa_wait1();           // tile t landed
        __syncthreads();
        const u32 base = sb + (u32)(t & 1) * BUFSZ;

        // ---- prefetch pos (overlaps S MMAs) ----
        float2 pvA[8], pvB[8];
#pragma unroll
        for (int nn = 0; nn < 8; nn++) {
            int col = kv0 + nn * 8 + (lane & 3) * 2;
            if (col < LKV) {
                pvA[nn] = *(const float2*)(posA + col);
                pvB[nn] = *(const float2*)(posB + col);
            } else {
                pvA[nn] = make_float2(0.f, 0.f);
                pvB[nn] = make_float2(0.f, 0.f);
            }
        }

        // ---- S = Qhi.Khi + Qlo.Khi ----
        float sacc[8][4];
#pragma unroll
        for (int n = 0; n < 8; n++)
#pragma unroll
            for (int j = 0; j < 4; j++) sacc[n][j] = 0.0f;

#pragma unroll
        for (int nn = 0; nn < 8; nn++) {
            u32 koff = base + (u32)((nn * 8 + (l16 & 7)) * KSTB + (l16 >> 3) * 16);
#pragma unroll
            for (int ks = 0; ks < 3; ks++) {
                u32 bh2[2];
                ldmx2(bh2, koff + ks * 32);
                mma16816(sacc[nn], qfh[ks], bh2);
                mma16816(sacc[nn], qfl[ks], bh2);
            }
        }

        // ---- softmax: p = exp(s + pos - M_FIX) ----
#pragma unroll
        for (int nn = 0; nn < 8; nn++) {
            int col = kv0 + nn * 8 + (lane & 3) * 2;
            if (col < LKV) {
                float p0 = __expf(sacc[nn][0] + pvA[nn].x - M_FIX);
                float p1 = __expf(sacc[nn][1] + pvA[nn].y - M_FIX);
                float p2 = __expf(sacc[nn][2] + pvB[nn].x - M_FIX);
                float p3 = __expf(sacc[nn][3] + pvB[nn].y - M_FIX);
                sacc[nn][0] = p0; sacc[nn][1] = p1;
                sacc[nn][2] = p2; sacc[nn][3] = p3;
                lsum0 += p0 + p1;
                lsum1 += p2 + p3;
            } else {
                sacc[nn][0] = 0.f; sacc[nn][1] = 0.f;
                sacc[nn][2] = 0.f; sacc[nn][3] = 0.f;
            }
        }

        // ---- O += Phi.Vhi + Plo.Vhi + Phi.Vlo ----
#pragma unroll
        for (int kk = 0; kk < 4; kk++) {
            u32 pah[4], pal[4];
#pragma unroll
            for (int half = 0; half < 2; half++) {
                int cn = 2 * kk + half;
                float p0 = sacc[cn][0], p1 = sacc[cn][1];
                float p2 = sacc[cn][2], p3 = sacc[cn][3];
                float h0 = __bfloat162float(__float2bfloat16(p0));
                float h1 = __bfloat162float(__float2bfloat16(p1));
                float h2 = __bfloat162float(__float2bfloat16(p2));
                float h3 = __bfloat162float(__float2bfloat16(p3));
                if (half == 0) {
                    pah[0] = cvt2bf(p0, p1);
                    pah[1] = cvt2bf(p2, p3);
                    pal[0] = cvt2bf(p0 - h0, p1 - h1);
                    pal[1] = cvt2bf(p2 - h2, p3 - h3);
                } else {
                    pah[2] = cvt2bf(p0, p1);
                    pah[3] = cvt2bf(p2, p3);
                    pal[2] = cvt2bf(p0 - h0, p1 - h1);
                    pal[3] = cvt2bf(p2 - h2, p3 - h3);
                }
            }
#pragma unroll
            for (int nd = 0; nd < 6; nd++) {
                u32 voff = base + (u32)((kk * 16 + l16) * KSTB + nd * 16);
                u32 vfh[2], vfl[2];
                ldmx2t(vfh, voff + R_VH);
                ldmx2t(vfl, voff + R_VL);
                mma16816(oacc[nd], pah, vfh);
                mma16816(oacc[nd], pal, vfh);
                mma16816(oacc[nd], pah, vfl);
            }
        }

        __syncthreads();       // this buffer's reads done -> refill
        if (t + 2 < NT) cp_fill(base, t + 2);
        cpa_commit();
    }

    lsum0 += __shfl_xor_sync(0xffffffffu, lsum0, 1);
    lsum0 += __shfl_xor_sync(0xffffffffu, lsum0, 2);
    lsum1 += __shfl_xor_sync(0xffffffffu, lsum1, 1);
    lsum1 += __shfl_xor_sync(0xffffffffu, lsum1, 2);
    float inv0 = 1.0f / lsum0;
    float inv1 = 1.0f / lsum1;

    size_t baseA = ((size_t)(b * LQ + rowA)) * DIM + h * HD;
    size_t baseB = baseA + (size_t)8 * DIM;
#pragma unroll
    for (int nd = 0; nd < 6; nd++) {
        int c = nd * 8 + (lane & 3) * 2;
        float a0 = oacc[nd][0] * inv0, a1 = oacc[nd][1] * inv0;
        float b0 = oacc[nd][2] * inv1, b1 = oacc[nd][3] * inv1;
        __nv_bfloat16 ha0 = __float2bfloat16(a0), ha1 = __float2bfloat16(a1);
        __nv_bfloat16 hb0 = __float2bfloat16(b0), hb1 = __float2bfloat16(b1);
        *(u32*)(g_xhi + baseA + c) = packbf(ha0, ha1);
        *(u32*)(g_xlo + baseA + c) = cvt2bf(a0 - __bfloat162float(ha0),
                                            a1 - __bfloat162float(ha1));
        *(u32*)(g_xhi + baseB + c) = packbf(hb0, hb1);
        *(u32*)(g_xlo + baseB + c) = cvt2bf(b0 - __bfloat162float(hb0),
                                            b1 - __bfloat162float(hb1));
    }
}

// ---------------------------------------------------------------------------
extern "C" void kernel_launch(void* const* d_in, const int* in_sizes, int n_in,
                              void* d_out, int out_size)
{
    const float* tem_mask    = (const float*)d_in[0];
    const float* search_mask = (const float*)d_in[1];
    const float* q           = (const float*)d_in[2];
    const float* kv          = (const float*)d_in[3];
    const float* attn_pos    = (const float*)d_in[4];
    const float* q_w         = (const float*)d_in[5];
    const float* q_b         = (const float*)d_in[6];
    const float* kv_w        = (const float*)d_in[7];
    const float* kv_b        = (const float*)d_in[8];
    const float* proj_w      = (const float*)d_in[9];
    const float* proj_b      = (const float*)d_in[10];
    float* out = (float*)d_out;

    __nv_bfloat16 *ahi, *alo, *whi, *wlo, *xhi, *xlo;
    cudaGetSymbolAddress((void**)&ahi, g_ahi);
    cudaGetSymbolAddress((void**)&alo, g_alo);
    cudaGetSymbolAddress((void**)&whi, g_whi);
    cudaGetSymbolAddress((void**)&wlo, g_wlo);
    cudaGetSymbolAddress((void**)&xhi, g_xhi);
    cudaGetSymbolAddress((void**)&xlo, g_xlo);

    const int n4_q  = B * LQ * DIM / 4;
    const int n4_kv = B * LKV * DIM / 4;
    const int n4_qw = DIM * DIM / 4;
    const int n4_kw = 2 * DIM * DIM / 4;

    ps_split<<<(n4_q + 255) / 256, 256>>>((const float4*)q, (uint2*)ahi, (uint2*)alo, n4_q);
    ps_split<<<(n4_qw + 255) / 256, 256>>>((const float4*)q_w, (uint2*)whi, (uint2*)wlo, n4_qw);
    mgemm_kernel<0><<<dim3(3, 128), 256>>>(ahi, alo, whi, wlo, q_b, nullptr, nullptr, nullptr);

    ps_split<<<(n4_kv + 255) / 256, 256>>>((const float4*)kv, (uint2*)ahi, (uint2*)alo, n4_kv);
    ps_split<<<(n4_kw + 255) / 256, 256>>>((const float4*)kv_w, (uint2*)whi, (uint2*)wlo, n4_kw);
    mgemm_kernel<1><<<dim3(6, 178), 256>>>(ahi, alo, whi, wlo, kv_b, tem_mask, search_mask, nullptr);

    attn_kernel<<<B * H * (LQ / 64), 128>>>(attn_pos);

    ps_split<<<(n4_qw + 255) / 256, 256>>>((const float4*)proj_w, (uint2*)whi, (uint2*)wlo, n4_qw);
    mgemm_kernel<2><<<dim3(3, 128), 256>>>(xhi, xlo, whi, wlo, proj_b, nullptr, nullptr, out);
}

// round 12
// speedup vs baseline: 2.3317x; 2.0468x over previous
#include <cuda_runtime.h>
#include <cuda_fp16.h>
#include <stdint.h>

// ---------------------------------------------------------------------------
// B=16, Lq=1024, Lkv=1424, DIM=384, HEADS=8, HEAD_DIM=48, TEM_LEN=400
// Whole datapath single-product fp16 on mma.sync tensor cores:
//   ps_cvt: fp32 -> fp16 once per operand
//   projections: fp16 GEMM, cp.async double-buffered
//   attention: fp16 flash, cp.async double-buffered K/V, fixed-max softmax
// Error model (calibrated on R10 measurement): ~3-4e-4 final.
// ---------------------------------------------------------------------------

constexpr int B    = 16;
constexpr int H    = 8;
constexpr int DIM  = 384;
constexpr int HD   = 48;
constexpr int LQ   = 1024;
constexpr int LKV  = 1424;
constexpr int TEM  = 400;
constexpr float ATTN_SCALE = 0.14433756729740643f;  // 48^-0.5
constexpr float M_FIX = 4.0f;   // fixed softmax max; p stays in fp16 normal range

using u32 = unsigned int;

// ---- scratch ---------------------------------------------------------------
__device__ __half g_ah[B * LKV * DIM];      // fp16 A operand (q, then kv)
__device__ __half g_wh[2 * DIM * DIM];      // fp16 W operand
__device__ __half g_qh[B * H * LQ * HD];    // (b,h,q,d) pre-scaled
__device__ __half g_kh[B * H * LKV * HD];   // (b,h,s,d)
__device__ __half g_vh[B * H * LKV * HD];   // (b,h,s,d) row-major (+masks)
__device__ __half g_xh[B * LQ * DIM];       // attention output, fp16

// ---- wrappers --------------------------------------------------------------
__device__ __forceinline__ u32 smu32(const void* p) {
    u32 a;
    asm("{ .reg .u64 t; cvta.to.shared.u64 t, %1; cvt.u32.u64 %0, t; }"
        : "=r"(a) : "l"(p));
    return a;
}
__device__ __forceinline__ void ldmx4(u32* r, u32 addr) {
    asm volatile("ldmatrix.sync.aligned.m8n8.x4.shared.b16 {%0,%1,%2,%3}, [%4];"
                 : "=r"(r[0]), "=r"(r[1]), "=r"(r[2]), "=r"(r[3]) : "r"(addr));
}
__device__ __forceinline__ void ldmx2(u32* r, u32 addr) {
    asm volatile("ldmatrix.sync.aligned.m8n8.x2.shared.b16 {%0,%1}, [%2];"
                 : "=r"(r[0]), "=r"(r[1]) : "r"(addr));
}
__device__ __forceinline__ void ldmx2t(u32* r, u32 addr) {
    asm volatile("ldmatrix.sync.aligned.m8n8.x2.trans.shared.b16 {%0,%1}, [%2];"
                 : "=r"(r[0]), "=r"(r[1]) : "r"(addr));
}
__device__ __forceinline__ void mma16816(float* d, const u32* a, const u32* b) {
    asm volatile(
        "mma.sync.aligned.m16n8k16.row.col.f32.f16.f16.f32 "
        "{%0,%1,%2,%3}, {%4,%5,%6,%7}, {%8,%9}, {%0,%1,%2,%3};"
        : "+f"(d[0]), "+f"(d[1]), "+f"(d[2]), "+f"(d[3])
        : "r"(a[0]), "r"(a[1]), "r"(a[2]), "r"(a[3]), "r"(b[0]), "r"(b[1]));
}
__device__ __forceinline__ u32 f2h2(float lo, float hi) {   // lo -> low 16 bits
    __half2 h = __floats2half2_rn(lo, hi);
    return *(u32*)&h;
}
__device__ __forceinline__ void cpa16(u32 dst, const void* src) {
    asm volatile("cp.async.cg.shared.global [%0], [%1], 16;"
                 :: "r"(dst), "l"(src));
}
__device__ __forceinline__ void cpa_commit() {
    asm volatile("cp.async.commit_group;");
}
__device__ __forceinline__ void cpa_wait1() {
    asm volatile("cp.async.wait_group 1;");
}

// ---------------------------------------------------------------------------
// ps_cvt: fp32 -> fp16 elementwise
// ---------------------------------------------------------------------------
__global__ void ps_cvt(const float4* __restrict__ src, uint2* __restrict__ dst, int n4)
{
    int i = blockIdx.x * blockDim.x + threadIdx.x;
    if (i >= n4) return;
    float4 v = src[i];
    dst[i] = make_uint2(f2h2(v.x, v.y), f2h2(v.z, v.w));
}

// ---------------------------------------------------------------------------
// fp16 single-product GEMM: out[m][n] = sum_k A[m][k] W[n][k] + bias[n], K=384
// Block 128x128, 256 threads (8 warps: 4m x 2n); cp.async double-buffered.
// MODE 0: q-proj -> g_qh (pre-scaled)   MODE 1: kv-proj -> g_kh/g_vh (+masks)
// MODE 2: out-proj -> fp32 d_out (A = g_xh)
// ---------------------------------------------------------------------------
constexpr int GROWB = 80;       // bytes per smem row (40 halfs) -> conflict-free
constexpr int GOPB  = 10240;    // one operand array: 128 * 80
constexpr int GSTAGE = 20480;   // A + B per stage

template <int MODE>
__device__ __forceinline__ void scatter_elem(
    int m, int n, float v,
    const float* __restrict__ bias,
    const float* __restrict__ tmask, const float* __restrict__ smask,
    float* __restrict__ out)
{
    v += bias[n];
    if (MODE == 0) {
        int b  = m >> 10;
        int qi = m & 1023;
        int h  = n / HD;
        int d  = n - h * HD;
        g_qh[((size_t)(b * H + h) * LQ + qi) * HD + d] = __float2half(v * ATTN_SCALE);
    } else if (MODE == 1) {
        int b = m / LKV;
        int s = m - b * LKV;
        if (n < DIM) {
            int h = n / HD, d = n - h * HD;
            g_kh[((size_t)(b * H + h) * LKV + s) * HD + d] = __float2half(v);
        } else {
            int nv = n - DIM;
            float mv = (s < TEM)
                ? tmask[((size_t)(b * TEM + s)) * DIM + nv]
                : smask[((size_t)(b * (LKV - TEM) + (s - TEM))) * DIM + nv];
            int h = nv / HD, d = nv - h * HD;
            g_vh[((size_t)(b * H + h) * LKV + s) * HD + d] = __float2half(v + mv);
        }
    } else {
        out[(size_t)m * DIM + n] = v;
    }
}

template <int MODE>
__global__ __launch_bounds__(256) void mgemm_kernel(
    const __half* __restrict__ A, const __half* __restrict__ W,
    const float* __restrict__ bias,
    const float* __restrict__ tmask, const float* __restrict__ smask,
    float* __restrict__ out)
{
    __shared__ __align__(16) char sm[2 * GSTAGE];
    const u32 sb = smu32(sm);

    const int m0   = blockIdx.y * 128;
    const int n0   = blockIdx.x * 128;
    const int tid  = threadIdx.x;
    const int warp = tid >> 5;
    const int lane = tid & 31;
    const int l16  = lane & 15;
    const int wm   = warp & 3;      // 4 m-strips of 32
    const int wn   = warp >> 2;     // 2 n-strips of 64

    // async fill of one 128x32 A tile + 128x32 W tile
    auto fill = [&](u32 stage, int k0) {
#pragma unroll
        for (int l = 0; l < 4; l++) {
            int i   = tid + 256 * l;       // 0..1023
            int arr = i >> 9;              // 0:A 1:B
            int rem = i & 511;
            int row = rem >> 2;
            int c   = rem & 3;
            const __half* src = (arr ? W + (size_t)(n0 + row) * DIM
                                     : A + (size_t)(m0 + row) * DIM) + k0 + c * 8;
            cpa16(stage + arr * GOPB + row * GROWB + c * 16, src);
        }
    };

    fill(sb, 0);          cpa_commit();
    fill(sb + GSTAGE, 32); cpa_commit();

    float acc[2][8][4];
#pragma unroll
    for (int mi = 0; mi < 2; mi++)
#pragma unroll
        for (int nj = 0; nj < 8; nj++)
#pragma unroll
            for (int j = 0; j < 4; j++) acc[mi][nj][j] = 0.0f;

    constexpr int NKC = DIM / 32;   // 12
    for (int kc = 0; kc < NKC; kc++) {
        cpa_wait1();
        __syncthreads();
        const u32 base = sb + (u32)(kc & 1) * GSTAGE;

#pragma unroll
        for (int ks = 0; ks < 2; ks++) {
            u32 af[2][4];
#pragma unroll
            for (int mi = 0; mi < 2; mi++) {
                u32 aoff = base + (u32)((wm * 32 + mi * 16 + l16) * GROWB
                                        + (lane >> 4) * 16 + ks * 32);
                ldmx4(af[mi], aoff);
            }
#pragma unroll
            for (int nj = 0; nj < 8; nj++) {
                u32 boff = base + GOPB + (u32)((wn * 64 + nj * 8 + (l16 & 7)) * GROWB
                                               + (l16 >> 3) * 16 + ks * 32);
                u32 bf[2];
                ldmx2(bf, boff);
                mma16816(acc[0][nj], af[0], bf);
                mma16816(acc[1][nj], af[1], bf);
            }
        }

        __syncthreads();
        if (kc + 2 < NKC) fill(base, (kc + 2) * 32);
        cpa_commit();
    }

#pragma unroll
    for (int mi = 0; mi < 2; mi++) {
#pragma unroll
        for (int rh = 0; rh < 2; rh++) {
            int m = m0 + wm * 32 + mi * 16 + rh * 8 + (lane >> 2);
#pragma unroll
            for (int nj = 0; nj < 8; nj++) {
                int n = n0 + wn * 64 + nj * 8 + (lane & 3) * 2;
                scatter_elem<MODE>(m, n,     acc[mi][nj][rh * 2 + 0], bias, tmask, smask, out);
                scatter_elem<MODE>(m, n + 1, acc[mi][nj][rh * 2 + 1], bias, tmask, smask, out);
            }
        }
    }
}

// ---------------------------------------------------------------------------
// fp16 flash attention, cp.async double-buffered.
// Block = (b, h, 64-q tile), 128 threads (4 warps).
// S = Q.K (1 product), PV = P.V (1 product), fixed-max softmax.
// smem: buf0 [0,14336): Kh@0, Vh@7168 ; buf1 [14336,28672) overlays Q staging.
// ---------------------------------------------------------------------------
constexpr int KSTB  = 112;     // bytes per smem row (48 halfs + pad)
constexpr int R_V   = 7168;
constexpr int ABUF  = 14336;
constexpr int SMQ   = 14336;   // Q staging (dead after fragment extraction)

__global__ __launch_bounds__(128) void attn_kernel(const float* __restrict__ pos)
{
    __shared__ __align__(16) char sm[28672];
    const u32 sb = smu32(sm);

    const int tid   = threadIdx.x;
    const int warp  = tid >> 5;
    const int lane  = tid & 31;
    const int l16   = lane & 15;
    const int bid   = blockIdx.x;
    const int b     = bid & 15;            // batch fastest: pos L2 reuse x16
    const int qt    = (bid >> 4) & 15;
    const int h     = bid >> 8;
    const int q0    = qt * 64;
    const int bh    = b * H + h;
    const int qrow0 = warp * 16;

    const __half* kh = g_kh + (size_t)bh * LKV * HD;
    const __half* vh = g_vh + (size_t)bh * LKV * HD;

    // async fill of one kv tile (Kh + Vh, 64 rows x 96B each)
    auto cp_fill = [&](u32 bufbase, int tile) {
        const int kv0 = tile * 64;
#pragma unroll
        for (int l = 0; l < 6; l++) {
            int i   = tid + 128 * l;          // 0..767
            int arr = i / 384;
            int rem = i - arr * 384;
            int row = rem / 6;
            int ch  = rem - row * 6;
            int srow = kv0 + row; if (srow >= LKV) srow = LKV - 1;
            const __half* src = (arr ? vh : kh) + (size_t)srow * HD + ch * 8;
            cpa16(bufbase + arr * R_V + row * KSTB + ch * 16, src);
        }
    };

    // ---- Q staging (overlays buf1) + start tile0 fill into buf0 ----
    {
        const __half* qh = g_qh + ((size_t)bh * LQ + q0) * HD;
#pragma unroll
        for (int l = 0; l < 3; l++) {
            int idx = tid + 128 * l;
            int row = idx / 6, c = idx % 6;
            *(uint4*)(sm + SMQ + row * KSTB + c * 16) = *(const uint4*)(qh + row * HD + c * 8);
        }
    }
    cp_fill(sb, 0);
    cpa_commit();
    __syncthreads();

    // ---- Q fragments (registers, all kv tiles) ----
    u32 qf[3][4];
    {
        u32 qo = (u32)((qrow0 + l16) * KSTB + (lane >> 4) * 16);
#pragma unroll
        for (int ks = 0; ks < 3; ks++)
            ldmx4(qf[ks], sb + SMQ + qo + ks * 32);
    }
    __syncthreads();           // Q staging dead -> buf1 may be filled
    cp_fill(sb + ABUF, 1);
    cpa_commit();

    const int rowA = q0 + qrow0 + (lane >> 2);
    const float* posA = pos + ((size_t)h * LQ + rowA) * LKV;
    const float* posB = posA + (size_t)8 * LKV;

    float oacc[6][4];
#pragma unroll
    for (int n = 0; n < 6; n++)
#pragma unroll
        for (int j = 0; j < 4; j++) oacc[n][j] = 0.0f;
    float lsum0 = 0.0f, lsum1 = 0.0f;

    constexpr int NT = (LKV + 63) / 64;  // 23

    for (int t = 0; t < NT; t++) {
        const int kv0 = t * 64;
        cpa_wait1();
        __syncthreads();
        const u32 base = sb + (u32)(t & 1) * ABUF;

        // ---- prefetch pos (overlaps S MMAs) ----
        float2 pvA[8], pvB[8];
#pragma unroll
        for (int nn = 0; nn < 8; nn++) {
            int col = kv0 + nn * 8 + (lane & 3) * 2;
            if (col < LKV) {
                pvA[nn] = *(const float2*)(posA + col);
                pvB[nn] = *(const float2*)(posB + col);
            } else {
                pvA[nn] = make_float2(0.f, 0.f);
                pvB[nn] = make_float2(0.f, 0.f);
            }
        }

        // ---- S = Q.K ----
        float sacc[8][4];
#pragma unroll
        for (int n = 0; n < 8; n++)
#pragma unroll
            for (int j = 0; j < 4; j++) sacc[n][j] = 0.0f;

#pragma unroll
        for (int nn = 0; nn < 8; nn++) {
            u32 koff = base + (u32)((nn * 8 + (l16 & 7)) * KSTB + (l16 >> 3) * 16);
#pragma unroll
            for (int ks = 0; ks < 3; ks++) {
                u32 bf[2];
                ldmx2(bf, koff + ks * 32);
                mma16816(sacc[nn], qf[ks], bf);
            }
        }

        // ---- softmax: p = exp(s + pos - M_FIX) ----
#pragma unroll
        for (int nn = 0; nn < 8; nn++) {
            int col = kv0 + nn * 8 + (lane & 3) * 2;
            if (col < LKV) {
                float p0 = __expf(sacc[nn][0] + pvA[nn].x - M_FIX);
                float p1 = __expf(sacc[nn][1] + pvA[nn].y - M_FIX);
                float p2 = __expf(sacc[nn][2] + pvB[nn].x - M_FIX);
                float p3 = __expf(sacc[nn][3] + pvB[nn].y - M_FIX);
                sacc[nn][0] = p0; sacc[nn][1] = p1;
                sacc[nn][2] = p2; sacc[nn][3] = p3;
                lsum0 += p0 + p1;
                lsum1 += p2 + p3;
            } else {
                sacc[nn][0] = 0.f; sacc[nn][1] = 0.f;
                sacc[nn][2] = 0.f; sacc[nn][3] = 0.f;
            }
        }

        // ---- O += P.V ----
#pragma unroll
        for (int kk = 0; kk < 4; kk++) {
            u32 pa[4];
            // a0=(row g, k lo 8), a1=(row g+8, k lo), a2=(row g, k hi), a3=(row g+8, k hi)
            pa[0] = f2h2(sacc[2 * kk][0],     sacc[2 * kk][1]);
            pa[1] = f2h2(sacc[2 * kk][2],     sacc[2 * kk][3]);
            pa[2] = f2h2(sacc[2 * kk + 1][0], sacc[2 * kk + 1][1]);
            pa[3] = f2h2(sacc[2 * kk + 1][2], sacc[2 * kk + 1][3]);
#pragma unroll
            for (int nd = 0; nd < 6; nd++) {
                u32 voff = base + R_V + (u32)((kk * 16 + l16) * KSTB + nd * 16);
                u32 vf[2];
                ldmx2t(vf, voff);
                mma16816(oacc[nd], pa, vf);
            }
        }

        __syncthreads();       // this buffer's reads done -> refill
        if (t + 2 < NT) cp_fill(base, t + 2);
        cpa_commit();
    }

    lsum0 += __shfl_xor_sync(0xffffffffu, lsum0, 1);
    lsum0 += __shfl_xor_sync(0xffffffffu, lsum0, 2);
    lsum1 += __shfl_xor_sync(0xffffffffu, lsum1, 1);
    lsum1 += __shfl_xor_sync(0xffffffffu, lsum1, 2);
    float inv0 = 1.0f / lsum0;
    float inv1 = 1.0f / lsum1;

    size_t baseA = ((size_t)(b * LQ + rowA)) * DIM + h * HD;
    size_t baseB = baseA + (size_t)8 * DIM;
#pragma unroll
    for (int nd = 0; nd < 6; nd++) {
        int c = nd * 8 + (lane & 3) * 2;
        *(u32*)(g_xh + baseA + c) = f2h2(oacc[nd][0] * inv0, oacc[nd][1] * inv0);
        *(u32*)(g_xh + baseB + c) = f2h2(oacc[nd][2] * inv1, oacc[nd][3] * inv1);
    }
}

// ---------------------------------------------------------------------------
extern "C" void kernel_launch(void* const* d_in, const int* in_sizes, int n_in,
                              void* d_out, int out_size)
{
    const float* tem_mask    = (const float*)d_in[0];
    const float* search_mask = (const float*)d_in[1];
    const float* q           = (const float*)d_in[2];
    const float* kv          = (const float*)d_in[3];
    const float* attn_pos    = (const float*)d_in[4];
    const float* q_w         = (const float*)d_in[5];
    const float* q_b         = (const float*)d_in[6];
    const float* kv_w        = (const float*)d_in[7];
    const float* kv_b        = (const float*)d_in[8];
    const float* proj_w      = (const float*)d_in[9];
    const float* proj_b      = (const float*)d_in[10];
    float* out = (float*)d_out;

    __half *ah, *wh, *xh;
    cudaGetSymbolAddress((void**)&ah, g_ah);
    cudaGetSymbolAddress((void**)&wh, g_wh);
    cudaGetSymbolAddress((void**)&xh, g_xh);

    const int n4_q  = B * LQ * DIM / 4;
    const int n4_kv = B * LKV * DIM / 4;
    const int n4_qw = DIM * DIM / 4;
    const int n4_kw = 2 * DIM * DIM / 4;

    // q projection
    ps_cvt<<<(n4_q + 255) / 256, 256>>>((const float4*)q, (uint2*)ah, n4_q);
    ps_cvt<<<(n4_qw + 255) / 256, 256>>>((const float4*)q_w, (uint2*)wh, n4_qw);
    mgemm_kernel<0><<<dim3(3, 128), 256>>>(ah, wh, q_b, nullptr, nullptr, nullptr);

    // kv projection
    ps_cvt<<<(n4_kv + 255) / 256, 256>>>((const float4*)kv, (uint2*)ah, n4_kv);
    ps_cvt<<<(n4_kw + 255) / 256, 256>>>((const float4*)kv_w, (uint2*)wh, n4_kw);
    mgemm_kernel<1><<<dim3(6, 178), 256>>>(ah, wh, kv_b, tem_mask, search_mask, nullptr);

    // attention
    attn_kernel<<<B * H * (LQ / 64), 128>>>(attn_pos);

    // output projection
    ps_cvt<<<(n4_qw + 255) / 256, 256>>>((const float4*)proj_w, (uint2*)wh, n4_qw);
    mgemm_kernel<2><<<dim3(3, 128), 256>>>(xh, wh, proj_b, nullptr, nullptr, out);
}